// round 9
// baseline (speedup 1.0000x reference)
#include <cuda_runtime.h>
#include <cuda_fp16.h>
#include <math.h>
#include <stdint.h>

// ---------------- problem constants ----------------
#define ROWS   65536
#define CDIM   512
#define QKVC   1536
#define NHEAD  16
#define BWIN   1024
// ----------------------------------------------------

// Scratch (device globals: allocation-free)
__device__ __align__(16) __half g_qkvh[(size_t)ROWS * QKVC];  // qkv in half (q pre-scaled)
__device__ __align__(16) __half g_Ah[(size_t)ROWS * 1024];    // [fine|coarse] concat, half
__device__ __align__(16) __half g_xh[(size_t)ROWS * CDIM];    // x in half
__device__ __align__(16) __half g_Kgh[16 * 16 * 64 * 32];     // pooled K, half
__device__ __align__(16) __half g_Vgh[16 * 16 * 64 * 32];     // pooled V, half
__device__ __align__(16) float  g_W[1024 * 512];
__device__ __align__(16) __half g_WTh[512 * 1024];            // W^T [n][k] half
__device__ __align__(16) __half g_qwTh[QKVC * CDIM];          // qkv_w^T [n][k] half (q rows scaled)
__device__ __align__(16) float  g_qb[QKVC];                   // qkv_b (q part scaled)
__device__ __align__(16) float  g_bc[512];

__device__ __forceinline__ float f2tf32(float x) {
    unsigned r;
    asm("cvt.rna.tf32.f32 %0, %1;" : "=r"(r) : "f"(x));
    return __uint_as_float(r);
}
__device__ __forceinline__ uint32_t smem_u32(const void* p) {
    uint32_t a;
    asm("{ .reg .u64 t; cvta.to.shared.u64 t, %1; cvt.u32.u64 %0, t; }" : "=r"(a) : "l"(p));
    return a;
}
__device__ __forceinline__ uint32_t pack_h2(float lo, float hi) {
    __half2 h = __floats2half2_rn(lo, hi);
    return *(uint32_t*)&h;
}
#define CP_ASYNC16(dst, src) asm volatile("cp.async.cg.shared.global [%0], [%1], 16;" :: "r"(dst), "l"(src))
#define CP_COMMIT()          asm volatile("cp.async.commit_group;" ::: "memory")
#define CP_WAIT1()           asm volatile("cp.async.wait_group 1;" ::: "memory")

#define MMA_F16(acc, a0, a1, a2, a3, b0, b1) \
    asm volatile( \
        "mma.sync.aligned.m16n8k16.row.col.f32.f16.f16.f32 " \
        "{%0,%1,%2,%3},{%4,%5,%6,%7},{%8,%9},{%0,%1,%2,%3};" \
        : "+f"((acc)[0]), "+f"((acc)[1]), "+f"((acc)[2]), "+f"((acc)[3]) \
        : "r"(a0), "r"(a1), "r"(a2), "r"(a3), "r"(b0), "r"(b1))

#define MMA_TF32(acc, a, b) \
    asm volatile( \
        "mma.sync.aligned.m16n8k8.row.col.f32.tf32.tf32.f32 " \
        "{%0,%1,%2,%3},{%4,%5,%6,%7},{%8,%9},{%0,%1,%2,%3};" \
        : "+f"((acc)[0]), "+f"((acc)[1]), "+f"((acc)[2]), "+f"((acc)[3]) \
        : "r"(__float_as_uint((a)[0])), "r"(__float_as_uint((a)[1])), \
          "r"(__float_as_uint((a)[2])), "r"(__float_as_uint((a)[3])), \
          "r"(__float_as_uint((b)[0])), "r"(__float_as_uint((b)[1])))

#define LDSM4(r0, r1, r2, r3, addr) \
    asm volatile("ldmatrix.sync.aligned.m8n8.x4.shared.b16 {%0,%1,%2,%3}, [%4];" \
        : "=r"(r0), "=r"(r1), "=r"(r2), "=r"(r3) : "r"(addr))

// ============================================================
// FP16 tensor GEMM: C = A(MxK,half) @ B^T (+bias), B [n][k] half.
// Block 128x128 (128 thr, 4 warps of 64x64), BK=32, 3-stage cp.async,
// ldmatrix.x4 fragments, ONE barrier per k-iter. 2 CTAs/SM.
// ============================================================
#define HSTR   40                        // halves per smem row
#define HROWB  80                        // bytes per smem row
#define HBOFF  (128 * HROWB)             // B region offset in stage
#define HSTGB  (256 * HROWB)             // stage bytes (20480)
#define HNST   3
#define HSMEM  (HNST * HSTGB)            // 61440 bytes

template<bool HOUT>
__global__ __launch_bounds__(128, 2) void gemm_h(
    const __half* __restrict__ A, const __half* __restrict__ B,
    const float* __restrict__ bias, void* __restrict__ Cv,
    int M, int N, int K)
{
    extern __shared__ __half smh[];
    const uint32_t sbu = smem_u32(smh);

    const int tid  = threadIdx.x;
    const int warp = tid >> 5, lane = tid & 31;
    const int grp  = lane >> 2, tig = lane & 3;
    const int m0 = blockIdx.y * 128;
    const int n0 = blockIdx.x * 128;
    const int wm = (warp & 1) * 64;
    const int wn = (warp >> 1) * 64;

    const uint32_t aBase = (uint32_t)((wm + (lane & 15)) * HROWB + ((lane >> 4) * 16));
    const uint32_t bBase = (uint32_t)(HBOFF +
        (wn + (lane & 7) + ((lane >> 4) & 1) * 8) * HROWB + (((lane >> 3) & 1) * 16));

    float acc[4][8][4];
#pragma unroll
    for (int mi = 0; mi < 4; mi++)
#pragma unroll
        for (int ni = 0; ni < 8; ni++)
#pragma unroll
            for (int r = 0; r < 4; r++) acc[mi][ni][r] = 0.f;

    const int nk = K >> 5;

    auto load_stage = [&](int buf, int kc) {
        const __half* Ab = A + (size_t)m0 * K + kc * 32;
        const __half* Bb = B + (size_t)n0 * K + kc * 32;
        const uint32_t sA = sbu + (uint32_t)buf * HSTGB;
        const uint32_t sB = sA + HBOFF;
#pragma unroll
        for (int i = 0; i < 4; i++) {
            int e = tid + i * 128;
            int row = e >> 2, ch = e & 3;
            CP_ASYNC16(sA + (uint32_t)row * HROWB + ch * 16, Ab + (size_t)row * K + ch * 8);
            CP_ASYNC16(sB + (uint32_t)row * HROWB + ch * 16, Bb + (size_t)row * K + ch * 8);
        }
    };

    load_stage(0, 0); CP_COMMIT();
    if (nk > 1) load_stage(1, 1);
    CP_COMMIT();

    for (int kc = 0; kc < nk; kc++) {
        CP_WAIT1();            // stage kc arrived (<=1 newer group pending)
        __syncthreads();       // all warps done with buffer (kc+2)%3's old contents
        if (kc + 2 < nk) load_stage((kc + 2) % HNST, kc + 2);
        CP_COMMIT();

        const uint32_t sg = sbu + (uint32_t)(kc % HNST) * HSTGB;
#pragma unroll
        for (int ks = 0; ks < 2; ks++) {
            const uint32_t ko = ks * 32;
            uint32_t a[4][4], b[8][2];
#pragma unroll
            for (int mi = 0; mi < 4; mi++)
                LDSM4(a[mi][0], a[mi][1], a[mi][2], a[mi][3],
                      sg + aBase + mi * (16 * HROWB) + ko);
#pragma unroll
            for (int np = 0; np < 4; np++)
                LDSM4(b[2 * np][0], b[2 * np][1], b[2 * np + 1][0], b[2 * np + 1][1],
                      sg + bBase + np * (16 * HROWB) + ko);
#pragma unroll
            for (int mi = 0; mi < 4; mi++)
#pragma unroll
                for (int ni = 0; ni < 8; ni++)
                    MMA_F16(acc[mi][ni], a[mi][0], a[mi][1], a[mi][2], a[mi][3],
                            b[ni][0], b[ni][1]);
        }
    }

    // ---- epilogue ----
#pragma unroll
    for (int ni = 0; ni < 8; ni++) {
        const int col = n0 + wn + ni * 8 + tig * 2;
        const float b0 = bias ? bias[col]     : 0.f;
        const float b1 = bias ? bias[col + 1] : 0.f;
#pragma unroll
        for (int mi = 0; mi < 4; mi++) {
            const int row = m0 + wm + mi * 16 + grp;
            if (HOUT) {
                __half* C = (__half*)Cv;
                *(uint32_t*)(C + (size_t)row * N + col) =
                    pack_h2(acc[mi][ni][0] + b0, acc[mi][ni][1] + b1);
                *(uint32_t*)(C + (size_t)(row + 8) * N + col) =
                    pack_h2(acc[mi][ni][2] + b0, acc[mi][ni][3] + b1);
            } else {
                float* C = (float*)Cv;
                float2 v0, v1;
                v0.x = acc[mi][ni][0] + b0;  v0.y = acc[mi][ni][1] + b1;
                v1.x = acc[mi][ni][2] + b0;  v1.y = acc[mi][ni][3] + b1;
                *(float2*)(C + (size_t)row * N + col)       = v0;
                *(float2*)(C + (size_t)(row + 8) * N + col) = v1;
            }
        }
    }
}

// ============================================================
// tf32 mma GEMM for the two tiny 512^3 weight-prep GEMMs (B row-major [k][n])
// ============================================================
__global__ __launch_bounds__(256) void gemm_tf32(
    const float* __restrict__ A, const float* __restrict__ Bm,
    const float* __restrict__ bias, float* __restrict__ Cm,
    int M, int N, int K)
{
    __shared__ float As[2][16][132];
    __shared__ float Bs[2][16][132];

    const int t    = threadIdx.x;
    const int m0   = blockIdx.y * 128;
    const int n0   = blockIdx.x * 128;
    const int warp = t >> 5, lane = t & 31;
    const int grp  = lane >> 2, tig = lane & 3;
    const int wm   = (warp & 1) * 64;
    const int wn   = (warp >> 1) * 32;

    const int aRow0 = t >> 2;
    const int aCol  = (t & 3) * 4;
    const int bK0   = t >> 5;
    const int bCol  = (t & 31) * 4;

    const float* aP0 = A  + (size_t)(m0 + aRow0)      * K + aCol;
    const float* aP1 = A  + (size_t)(m0 + aRow0 + 64) * K + aCol;
    const float* bP0 = Bm + (size_t)bK0       * N + n0 + bCol;
    const float* bP1 = Bm + (size_t)(bK0 + 8) * N + n0 + bCol;

    float acc[4][4][4];
#pragma unroll
    for (int mi = 0; mi < 4; mi++)
#pragma unroll
        for (int ni = 0; ni < 4; ni++)
#pragma unroll
            for (int r = 0; r < 4; r++) acc[mi][ni][r] = 0.f;

    const int nk = K >> 4;
    float4 aReg[2], bReg[2];

    aReg[0] = *(const float4*)(aP0);
    aReg[1] = *(const float4*)(aP1);
    bReg[0] = *(const float4*)(bP0);
    bReg[1] = *(const float4*)(bP1);
    {
        As[0][aCol + 0][aRow0] = f2tf32(aReg[0].x);  As[0][aCol + 1][aRow0] = f2tf32(aReg[0].y);
        As[0][aCol + 2][aRow0] = f2tf32(aReg[0].z);  As[0][aCol + 3][aRow0] = f2tf32(aReg[0].w);
        As[0][aCol + 0][aRow0 + 64] = f2tf32(aReg[1].x);  As[0][aCol + 1][aRow0 + 64] = f2tf32(aReg[1].y);
        As[0][aCol + 2][aRow0 + 64] = f2tf32(aReg[1].z);  As[0][aCol + 3][aRow0 + 64] = f2tf32(aReg[1].w);
        float4 c0, c1;
        c0.x = f2tf32(bReg[0].x); c0.y = f2tf32(bReg[0].y);
        c0.z = f2tf32(bReg[0].z); c0.w = f2tf32(bReg[0].w);
        c1.x = f2tf32(bReg[1].x); c1.y = f2tf32(bReg[1].y);
        c1.z = f2tf32(bReg[1].z); c1.w = f2tf32(bReg[1].w);
        *(float4*)&Bs[0][bK0][bCol]     = c0;
        *(float4*)&Bs[0][bK0 + 8][bCol] = c1;
    }
    __syncthreads();

    for (int kc = 0; kc < nk; kc++) {
        const int buf = kc & 1;
        const bool has = (kc + 1) < nk;
        if (has) {
            const int ko = (kc + 1) * 16;
            aReg[0] = *(const float4*)(aP0 + ko);
            aReg[1] = *(const float4*)(aP1 + ko);
            bReg[0] = *(const float4*)(bP0 + (size_t)ko * N);
            bReg[1] = *(const float4*)(bP1 + (size_t)ko * N);
        }
#pragma unroll
        for (int ks = 0; ks < 2; ks++) {
            const int km = ks * 8;
            float a[4][4], b[4][2];
#pragma unroll
            for (int mi = 0; mi < 4; mi++) {
                const int rr = wm + mi * 16 + grp;
                a[mi][0] = As[buf][km + tig][rr];
                a[mi][1] = As[buf][km + tig][rr + 8];
                a[mi][2] = As[buf][km + tig + 4][rr];
                a[mi][3] = As[buf][km + tig + 4][rr + 8];
            }
#pragma unroll
            for (int ni = 0; ni < 4; ni++) {
                const int cc = wn + ni * 8 + grp;
                b[ni][0] = Bs[buf][km + tig][cc];
                b[ni][1] = Bs[buf][km + tig + 4][cc];
            }
#pragma unroll
            for (int mi = 0; mi < 4; mi++)
#pragma unroll
                for (int ni = 0; ni < 4; ni++)
                    MMA_TF32(acc[mi][ni], a[mi], b[ni]);
        }
        if (has) {
            const int bb = buf ^ 1;
            As[bb][aCol + 0][aRow0] = f2tf32(aReg[0].x);  As[bb][aCol + 1][aRow0] = f2tf32(aReg[0].y);
            As[bb][aCol + 2][aRow0] = f2tf32(aReg[0].z);  As[bb][aCol + 3][aRow0] = f2tf32(aReg[0].w);
            As[bb][aCol + 0][aRow0 + 64] = f2tf32(aReg[1].x);  As[bb][aCol + 1][aRow0 + 64] = f2tf32(aReg[1].y);
            As[bb][aCol + 2][aRow0 + 64] = f2tf32(aReg[1].z);  As[bb][aCol + 3][aRow0 + 64] = f2tf32(aReg[1].w);
            float4 c0, c1;
            c0.x = f2tf32(bReg[0].x); c0.y = f2tf32(bReg[0].y);
            c0.z = f2tf32(bReg[0].z); c0.w = f2tf32(bReg[0].w);
            c1.x = f2tf32(bReg[1].x); c1.y = f2tf32(bReg[1].y);
            c1.z = f2tf32(bReg[1].z); c1.w = f2tf32(bReg[1].w);
            *(float4*)&Bs[bb][bK0][bCol]     = c0;
            *(float4*)&Bs[bb][bK0 + 8][bCol] = c1;
        }
        __syncthreads();
    }

#pragma unroll
    for (int ni = 0; ni < 4; ni++) {
        const int col = n0 + wn + ni * 8 + tig * 2;
        float b0 = bias ? bias[col]     : 0.f;
        float b1 = bias ? bias[col + 1] : 0.f;
#pragma unroll
        for (int mi = 0; mi < 4; mi++) {
            const int row = m0 + wm + mi * 16 + grp;
            float2 v0, v1;
            v0.x = acc[mi][ni][0] + b0;  v0.y = acc[mi][ni][1] + b1;
            v1.x = acc[mi][ni][2] + b0;  v1.y = acc[mi][ni][3] + b1;
            *(float2*)(Cm + (size_t)row * N + col)       = v0;
            *(float2*)(Cm + (size_t)(row + 8) * N + col) = v1;
        }
    }
}

// ============================================================
// transpose + half round: dst(half)[c][r] = h(src[r][c] * (c<scaleRows ? s : 1))
// ============================================================
__global__ void transpose_h(const float* __restrict__ src, __half* __restrict__ dst,
                            int R, int Cc, int scaleRows, float s)
{
    __shared__ float tile[32][33];
    const int bx = blockIdx.x * 32, by = blockIdx.y * 32;
    const int tx = threadIdx.x, ty = threadIdx.y;
#pragma unroll
    for (int i = 0; i < 4; i++)
        tile[ty + i * 8][tx] = src[(size_t)(by + ty + i * 8) * Cc + bx + tx];
    __syncthreads();
#pragma unroll
    for (int i = 0; i < 4; i++) {
        int drow = bx + ty + i * 8;
        float v = tile[tx][ty + i * 8];
        if (drow < scaleRows) v *= s;
        dst[(size_t)drow * R + by + tx] = __float2half_rn(v);
    }
}

// qkv bias with q part pre-scaled
__global__ void scale_qb(const float* __restrict__ qkv_b)
{
    int j = blockIdx.x * 256 + threadIdx.x;
    if (j < QKVC) g_qb[j] = qkv_b[j] * (j < 512 ? 0.17677669529663687f : 1.0f);
}

// x -> half copy
__global__ void round_xh(const float* __restrict__ x)
{
    size_t i = (size_t)blockIdx.x * 256 + threadIdx.x;
    float4 v = ((const float4*)x)[i];
    uint2 o;
    o.x = pack_h2(v.x, v.y);
    o.y = pack_h2(v.z, v.w);
    ((uint2*)g_xh)[i] = o;
}

// ============================================================
// Pooled K/V: half source/dest, fp32 accumulation, half2 vector loads.
// One thread per (b,h,w,d-pair).
// ============================================================
__global__ void pool_kernel(const float* __restrict__ pool_w,
                            const float* __restrict__ pool_b)
{
    int p = blockIdx.x * 256 + threadIdx.x;     // 262144 pairs
    int d2 = p & 15;
    int w  = (p >> 4) & 63;
    int h  = (p >> 10) & 15;
    int b  = p >> 14;
    const __half* base = g_qkvh + (size_t)((b * 64 + w) * 64) * QKVC + h * 32 + d2 * 2;
    float k0 = 0.f, k1 = 0.f, v0 = 0.f, v1 = 0.f;
#pragma unroll 8
    for (int n = 0; n < 64; n++) {
        float pw = pool_w[n];
        __half2 kh = *(const __half2*)(base + (size_t)n * QKVC + 512);
        __half2 vh = *(const __half2*)(base + (size_t)n * QKVC + 1024);
        float2 kf = __half22float2(kh);
        float2 vf = __half22float2(vh);
        k0 += kf.x * pw;  k1 += kf.y * pw;
        v0 += vf.x * pw;  v1 += vf.y * pw;
    }
    float pb = pool_b[0];
    size_t o = (size_t)((b * 16 + h) * 64 + w) * 32 + d2 * 2;
    *(__half2*)(g_Kgh + o) = __floats2half2_rn(k0 + pb, k1 + pb);
    *(__half2*)(g_Vgh + o) = __floats2half2_rn(v0 + pb, v1 + pb);
}

// ============================================================
// Combined bias
// ============================================================
__global__ void bias_comb(const float* __restrict__ lpb, const float* __restrict__ gpb,
                          const float* __restrict__ pfw, const float* __restrict__ pfb)
{
    int j = blockIdx.x * 256 + threadIdx.x;
    if (j >= 512) return;
    float s = pfb[j];
    for (int c = 0; c < 512; c++) s += lpb[c] * pfw[c * 512 + j];
    for (int c = 0; c < 512; c++) s += gpb[c] * pfw[(512 + c) * 512 + j];
    g_bc[j] = s;
}

// ============================================================
// Tensor-core fused attention, zero mid-kernel barriers:
// ALL operands (incl. coarse pooled K/V) loaded up-front, one sync,
// then fine + coarse phases back-to-back (sP rows are warp-private).
// ============================================================
#define SQ_STR 40   // halves
#define SP_STR 72   // halves

__global__ __launch_bounds__(128) void attn_kernel(const float* __restrict__ lbt,
                                                   const float* __restrict__ gbt)
{
    const int head = blockIdx.x;
    const int bw   = blockIdx.y;
    const int b    = bw >> 6;
    const int t    = threadIdx.x;
    const int warp = t >> 5, lane = t & 31;
    const int grp  = lane >> 2, tig = lane & 3;

    __shared__ __half sQ[64 * SQ_STR];
    __shared__ __half sK[64 * SQ_STR];
    __shared__ __half sKg[64 * SQ_STR];
    __shared__ __half sVt[32 * SP_STR];
    __shared__ __half sVg[32 * SP_STR];
    __shared__ __half sP[64 * SP_STR];
    __shared__ float tabL[225], tabG[225];

    for (int i = t; i < 225; i += 128) {
        tabL[i] = lbt[i * 16 + head];
        tabG[i] = gbt[i * 16 + head];
    }
    {
        const __half* qbase = g_qkvh + (size_t)(bw * 64) * QKVC + head * 32;
        const __half* kgb   = g_Kgh + (size_t)((b * 16 + head) * 64) * 32;
        const __half* vgb   = g_Vgh + (size_t)((b * 16 + head) * 64) * 32;
        for (int i = t; i < 512; i += 128) {
            int n = i >> 3, d = (i & 7) * 4;
            uint2 q4 = *(const uint2*)(qbase + (size_t)n * QKVC + d);
            uint2 k4 = *(const uint2*)(qbase + (size_t)n * QKVC + 512 + d);
            uint2 v4 = *(const uint2*)(qbase + (size_t)n * QKVC + 1024 + d);
            uint2 kg = *(const uint2*)(kgb + n * 32 + d);
            uint2 vg = *(const uint2*)(vgb + n * 32 + d);
            *(uint32_t*)(sQ + n * SQ_STR + d)      = q4.x;
            *(uint32_t*)(sQ + n * SQ_STR + d + 2)  = q4.y;
            *(uint32_t*)(sK + n * SQ_STR + d)      = k4.x;
            *(uint32_t*)(sK + n * SQ_STR + d + 2)  = k4.y;
            *(uint32_t*)(sKg + n * SQ_STR + d)     = kg.x;
            *(uint32_t*)(sKg + n * SQ_STR + d + 2) = kg.y;
            __half2 v01 = *(__half2*)&v4.x;
            __half2 v23 = *(__half2*)&v4.y;
            sVt[(d + 0) * SP_STR + n] = __low2half(v01);
            sVt[(d + 1) * SP_STR + n] = __high2half(v01);
            sVt[(d + 2) * SP_STR + n] = __low2half(v23);
            sVt[(d + 3) * SP_STR + n] = __high2half(v23);
            __half2 g01 = *(__half2*)&vg.x;
            __half2 g23 = *(__half2*)&vg.y;
            sVg[(d + 0) * SP_STR + n] = __low2half(g01);
            sVg[(d + 1) * SP_STR + n] = __high2half(g01);
            sVg[(d + 2) * SP_STR + n] = __low2half(g23);
            sVg[(d + 3) * SP_STR + n] = __high2half(g23);
        }
    }
    __syncthreads();

    const int wrow = warp * 16;
    const int r0 = wrow + grp, r1 = r0 + 8;
    const int ri0 = r0 >> 3, ci0 = r0 & 7;
    const int ri1 = r1 >> 3, ci1 = r1 & 7;

    auto do_phase = [&](const float* tab, int outOff, const __half* sKx, const __half* sVx) {
        float s[8][4];
#pragma unroll
        for (int ni = 0; ni < 8; ni++)
#pragma unroll
            for (int r = 0; r < 4; r++) s[ni][r] = 0.f;
#pragma unroll
        for (int ks = 0; ks < 2; ks++) {
            const int km = ks * 16 + 2 * tig;
            uint32_t a0 = *(const uint32_t*)(sQ + r0 * SQ_STR + km);
            uint32_t a1 = *(const uint32_t*)(sQ + r1 * SQ_STR + km);
            uint32_t a2 = *(const uint32_t*)(sQ + r0 * SQ_STR + km + 8);
            uint32_t a3 = *(const uint32_t*)(sQ + r1 * SQ_STR + km + 8);
#pragma unroll
            for (int ni = 0; ni < 8; ni++) {
                uint32_t b0 = *(const uint32_t*)(sKx + (ni * 8 + grp) * SQ_STR + km);
                uint32_t b1 = *(const uint32_t*)(sKx + (ni * 8 + grp) * SQ_STR + km + 8);
                MMA_F16(s[ni], a0, a1, a2, a3, b0, b1);
            }
        }
        float mx0 = -1e30f, mx1 = -1e30f;
#pragma unroll
        for (int ni = 0; ni < 8; ni++) {
            const int c = ni * 8 + 2 * tig;
            const int rj0 = c >> 3,       cj0 = c & 7;
            const int rj1 = (c + 1) >> 3, cj1 = (c + 1) & 7;
            s[ni][0] += tab[(ri0 - rj0 + 7) * 15 + (ci0 - cj0 + 7)];
            s[ni][1] += tab[(ri0 - rj1 + 7) * 15 + (ci0 - cj1 + 7)];
            s[ni][2] += tab[(ri1 - rj0 + 7) * 15 + (ci1 - cj0 + 7)];
            s[ni][3] += tab[(ri1 - rj1 + 7) * 15 + (ci1 - cj1 + 7)];
            mx0 = fmaxf(mx0, fmaxf(s[ni][0], s[ni][1]));
            mx1 = fmaxf(mx1, fmaxf(s[ni][2], s[ni][3]));
        }
        mx0 = fmaxf(mx0, __shfl_xor_sync(0xffffffffu, mx0, 1));
        mx0 = fmaxf(mx0, __shfl_xor_sync(0xffffffffu, mx0, 2));
        mx1 = fmaxf(mx1, __shfl_xor_sync(0xffffffffu, mx1, 1));
        mx1 = fmaxf(mx1, __shfl_xor_sync(0xffffffffu, mx1, 2));
        float sum0 = 0.f, sum1 = 0.f;
#pragma unroll
        for (int ni = 0; ni < 8; ni++) {
            s[ni][0] = __expf(s[ni][0] - mx0);
            s[ni][1] = __expf(s[ni][1] - mx0);
            s[ni][2] = __expf(s[ni][2] - mx1);
            s[ni][3] = __expf(s[ni][3] - mx1);
            sum0 += s[ni][0] + s[ni][1];
            sum1 += s[ni][2] + s[ni][3];
        }
        sum0 += __shfl_xor_sync(0xffffffffu, sum0, 1);
        sum0 += __shfl_xor_sync(0xffffffffu, sum0, 2);
        sum1 += __shfl_xor_sync(0xffffffffu, sum1, 1);
        sum1 += __shfl_xor_sync(0xffffffffu, sum1, 2);
        const float inv0 = 1.f / sum0, inv1 = 1.f / sum1;
#pragma unroll
        for (int ni = 0; ni < 8; ni++) {
            const int c = ni * 8 + 2 * tig;
            *(uint32_t*)(sP + r0 * SP_STR + c) = pack_h2(s[ni][0] * inv0, s[ni][1] * inv0);
            *(uint32_t*)(sP + r1 * SP_STR + c) = pack_h2(s[ni][2] * inv1, s[ni][3] * inv1);
        }
        __syncwarp();
        float o[4][4];
#pragma unroll
        for (int ni = 0; ni < 4; ni++)
#pragma unroll
            for (int r = 0; r < 4; r++) o[ni][r] = 0.f;
#pragma unroll
        for (int ks = 0; ks < 4; ks++) {
            const int km = ks * 16 + 2 * tig;
            uint32_t a0 = *(const uint32_t*)(sP + r0 * SP_STR + km);
            uint32_t a1 = *(const uint32_t*)(sP + r1 * SP_STR + km);
            uint32_t a2 = *(const uint32_t*)(sP + r0 * SP_STR + km + 8);
            uint32_t a3 = *(const uint32_t*)(sP + r1 * SP_STR + km + 8);
#pragma unroll
            for (int ni = 0; ni < 4; ni++) {
                uint32_t b0 = *(const uint32_t*)(sVx + (ni * 8 + grp) * SP_STR + km);
                uint32_t b1 = *(const uint32_t*)(sVx + (ni * 8 + grp) * SP_STR + km + 8);
                MMA_F16(o[ni], a0, a1, a2, a3, b0, b1);
            }
        }
        __half* o0 = g_Ah + (size_t)(bw * 64 + r0) * 1024 + outOff + head * 32;
        __half* o1 = g_Ah + (size_t)(bw * 64 + r1) * 1024 + outOff + head * 32;
#pragma unroll
        for (int ni = 0; ni < 4; ni++) {
            const int c = ni * 8 + 2 * tig;
            *(uint32_t*)(o0 + c) = pack_h2(o[ni][0], o[ni][1]);
            *(uint32_t*)(o1 + c) = pack_h2(o[ni][2], o[ni][3]);
        }
    };

    do_phase(tabL, 0,   sK,  sVt);
    do_phase(tabG, 512, sKg, sVg);
}

// ============================================================
// launch  (order chosen so launch index 5 = QKV gemm_h for ncu -s 5)
// ============================================================
extern "C" void kernel_launch(void* const* d_in, const int* in_sizes, int n_in,
                              void* d_out, int out_size)
{
    (void)in_sizes; (void)n_in; (void)out_size;
    const float* x     = (const float*)d_in[0];
    const float* qkv_w = (const float*)d_in[1];
    const float* qkv_b = (const float*)d_in[2];
    const float* lbt   = (const float*)d_in[3];
    const float* gbt   = (const float*)d_in[4];
    const float* lpw   = (const float*)d_in[5];
    const float* lpb   = (const float*)d_in[6];
    const float* pw    = (const float*)d_in[7];
    const float* pb    = (const float*)d_in[8];
    const float* gpw   = (const float*)d_in[9];
    const float* gpb   = (const float*)d_in[10];
    const float* pfw   = (const float*)d_in[11];
    const float* pfb   = (const float*)d_in[12];
    float* out = (float*)d_out;

    float *gW, *gbc, *gqb;
    __half *gqkvh, *gAh, *gxh, *gWTh, *gqwTh;
    cudaGetSymbolAddress((void**)&gqkvh, g_qkvh);
    cudaGetSymbolAddress((void**)&gAh,   g_Ah);
    cudaGetSymbolAddress((void**)&gxh,   g_xh);
    cudaGetSymbolAddress((void**)&gW,    g_W);
    cudaGetSymbolAddress((void**)&gWTh,  g_WTh);
    cudaGetSymbolAddress((void**)&gqwTh, g_qwTh);
    cudaGetSymbolAddress((void**)&gbc,   g_bc);
    cudaGetSymbolAddress((void**)&gqb,   g_qb);

    cudaFuncSetAttribute(gemm_h<true>,  cudaFuncAttributeMaxDynamicSharedMemorySize, HSMEM);
    cudaFuncSetAttribute(gemm_h<false>, cudaFuncAttributeMaxDynamicSharedMemorySize, HSMEM);

    // 0-2: QKV prep
    scale_qb<<<6, 256>>>(qkv_b);
    round_xh<<<(ROWS * CDIM / 4) / 256, 256>>>(x);
    transpose_h<<<dim3(QKVC / 32, CDIM / 32), dim3(32, 8)>>>(qkv_w, gqwTh, CDIM, QKVC,
                                                             512, 0.17677669529663687f);
    // 3-4: combined projection weight halves
    gemm_tf32<<<dim3(4, 4), 256>>>(lpw, pfw,             nullptr, gW,             512, 512, 512);
    gemm_tf32<<<dim3(4, 4), 256>>>(gpw, pfw + 512 * 512, nullptr, gW + 512 * 512, 512, 512, 512);

    // 5: QKV projection (ncu captures this one)
    gemm_h<true><<<dim3(QKVC / 128, ROWS / 128), 128, HSMEM>>>(
        gxh, gqwTh, gqb, gqkvh, ROWS, QKVC, CDIM);

    // 6-7: finish projection-weight prep
    bias_comb<<<2, 256>>>(lpb, gpb, pfw, pfb);
    transpose_h<<<dim3(512 / 32, 1024 / 32), dim3(32, 8)>>>(gW, gWTh, 1024, 512, 0, 1.f);

    // 8: pooled K/V (half)
    pool_kernel<<<1024, 256>>>(pw, pb);

    // 9: fused fine + coarse attention -> g_Ah (half)
    attn_kernel<<<dim3(NHEAD, BWIN), 128>>>(lbt, gbt);

    // 10: out = [A_f | A_c] @ W + bc (fp32)
    gemm_h<false><<<dim3(512 / 128, ROWS / 128), 128, HSMEM>>>(
        gAh, gWTh, gbc, out, ROWS, 512, 1024);
}